// round 4
// baseline (speedup 1.0000x reference)
#include <cuda_runtime.h>
#include <cuda_bf16.h>
#include <cstddef>

#define RR    7
#define KS    15             // 2R+1
#define NK    (KS*KS)        // 225
#define BATCH 8
#define HI    512
#define WI    512
#define HO    256
#define WO    256
#define TY    4              // output rows per item
#define SW    (WO + 2*RR)    // 270 (x window incl. halo)
#define SWP   280            // padded smem row stride
#define NITEM (BATCH * (HO/TY) * KS)   // 7680
#define NCTA  592            // 148 SMs * 4 CTAs, exact
#define IPB   13             // ceil(7680/592)
#define BUFSZ (TY * SWP)     // 1120 floats per buffer
#define DYN_SMEM 46080       // caps occupancy at exactly 4 CTAs/SM

__global__ __launch_bounds__(256)
void adj_equality_kernel(const float* __restrict__ in, float* __restrict__ out)
{
    extern __shared__ float buf[];      // 2 * BUFSZ floats used

    const int tid = threadIdx.x;
    const int tx  = tid & 63;           // 0..63
    const int ty  = tid >> 6;           // 0..3
    const int lx  = tx * 4;

    const int t0   = blockIdx.x * IPB;
    const int tend = min(t0 + IPB, NITEM);

    int parity = 0;
    for (int t = t0; t < tend; ++t, parity ^= 1) {
        // item decode: dy fastest -> consecutive items reuse centers + rows
        const int dy = t % KS;
        const int sp = t / KS;
        const int yt = sp & 63;
        const int b  = sp >> 6;
        const int y0 = yt * TY;

        const float* __restrict__ inb = in + (size_t)b * HI * WI;
        float* __restrict__ bw = buf + parity * BUFSZ;

        // ---- load 4 neighbor rows (y0+dy-7 .. y0+dy-4), zero-padded,
        //      stride-2 downsample on the fly ----
        #pragma unroll
        for (int k = 0; k < 5; ++k) {   // 5*256 >= 4*270
            const int i = tid + k * 256;
            if (i < TY * SW) {
                const int r  = i / SW;
                const int c  = i - r * SW;
                const int ny = y0 + r + dy - RR;
                const int gx = c - RR;
                float v = 0.0f;
                if (ny >= 0 && ny < HO && gx >= 0 && gx < WO)
                    v = inb[(size_t)(ny * 2) * WI + (size_t)(gx * 2)];
                bw[r * SWP + c] = v;
            }
        }

        // ---- centers straight from global (L1-hot: same addr for 15 dy's) ----
        const int y = y0 + ty;
        const float c0 = inb[(size_t)(y * 2) * WI + (size_t)((lx + 0) * 2)];
        const float c1 = inb[(size_t)(y * 2) * WI + (size_t)((lx + 1) * 2)];
        const float c2 = inb[(size_t)(y * 2) * WI + (size_t)((lx + 2) * 2)];
        const float c3 = inb[(size_t)(y * 2) * WI + (size_t)((lx + 3) * 2)];

        __syncthreads();   // single sync per item (double-buffered smem)

        // ---- register window: 18 consecutive floats of this neighbor row ----
        float w[KS + 3];
        #pragma unroll
        for (int j = 0; j < KS + 3; ++j)
            w[j] = bw[ty * SWP + lx + j];

        float* __restrict__ outp = out + ((size_t)b * NK + (size_t)(dy * KS)) * HO * WO
                                       + (size_t)y * WO + lx;

        #pragma unroll
        for (int dx = 0; dx < KS; ++dx) {
            float4 v;
            v.x = (w[dx + 0] == c0) ? 1.0f : 0.0f;
            v.y = (w[dx + 1] == c1) ? 1.0f : 0.0f;
            v.z = (w[dx + 2] == c2) ? 1.0f : 0.0f;
            v.w = (w[dx + 3] == c3) ? 1.0f : 0.0f;
            *reinterpret_cast<float4*>(outp + (size_t)dx * HO * WO) = v;
        }
    }
}

extern "C" void kernel_launch(void* const* d_in, const int* in_sizes, int n_in,
                              void* d_out, int out_size)
{
    const float* segments = (const float*)d_in[0];
    float* out = (float*)d_out;

    adj_equality_kernel<<<NCTA, 256, DYN_SMEM>>>(segments, out);
}

// round 5
// speedup vs baseline: 1.1516x; 1.1516x over previous
#include <cuda_runtime.h>
#include <cuda_bf16.h>
#include <cstddef>

#define RR   7
#define KS   15            // 2R+1
#define NK   (KS*KS)       // 225
#define BATCH 8
#define HI   512
#define WI   512
#define HO   256
#define WO   256
#define TY   4             // output rows per block
#define SW   (WO + 2*RR)   // 270 (x window with halo)
#define SWP  280           // padded smem row stride (multiple of 4 -> 16B rows)
#define NBLK (BATCH * (HO/TY) * KS)   // 8*64*15 = 7680
#define DYN_SMEM 46080     // caps occupancy at 4 CTAs/SM (4*46080=184KB <= 228KB)

__global__ __launch_bounds__(256)
void adj_equality_kernel(const float* __restrict__ in, float* __restrict__ out)
{
    extern __shared__ float nb[];   // uses nb[0 .. 4*SWP)

    // item decode: (b, ytile, dy) with dy fastest
    const int item = blockIdx.x;
    const int dy   = item % KS;
    const int sp   = item / KS;          // 0..511
    const int yt   = sp & 63;            // 0..63
    const int b    = sp >> 6;            // 0..7
    const int y0   = yt * TY;

    const int tid = threadIdx.x;
    const int tx  = tid & 63;            // 0..63
    const int ty  = tid >> 6;            // 0..3
    const int lx  = tx * 4;

    const float* __restrict__ inb = in + (size_t)b * HI * WI;

    // ---- Fill: row group r = ty fills smem row r, columns tx, tx+64, ... ----
    // neighbor row (downsampled coords): ny = y0 + r + dy - RR
    {
        const int ny = y0 + ty + dy - RR;
        const bool yok = (ny >= 0) && (ny < HO);
        const float* __restrict__ irow = inb + (size_t)(ny * 2) * WI;
        float* __restrict__ srow = nb + ty * SWP;
        #pragma unroll
        for (int k = 0; k < 5; ++k) {    // 5*64 = 320 >= 270
            const int c = tx + k * 64;
            if (c < SW) {
                const int gx = c - RR;
                float v = 0.0f;
                if (yok && gx >= 0 && gx < WO)
                    v = irow[(size_t)(gx * 2)];
                srow[c] = v;
            }
        }
    }

    // ---- Centers straight from global (L2-hot) ----
    const int y = y0 + ty;
    const float* __restrict__ crow = inb + (size_t)(y * 2) * WI;
    const float c0 = crow[(size_t)((lx + 0) * 2)];
    const float c1 = crow[(size_t)((lx + 1) * 2)];
    const float c2 = crow[(size_t)((lx + 2) * 2)];
    const float c3 = crow[(size_t)((lx + 3) * 2)];

    __syncthreads();

    // ---- Register window: 20 floats via 5x LDS.128 (16B-aligned, conflict-free) ----
    const float4* __restrict__ wrow =
        reinterpret_cast<const float4*>(nb + ty * SWP + lx);
    float w[20];
    #pragma unroll
    for (int q = 0; q < 5; ++q) {
        const float4 v = wrow[q];
        w[q * 4 + 0] = v.x;
        w[q * 4 + 1] = v.y;
        w[q * 4 + 2] = v.z;
        w[q * 4 + 3] = v.w;
    }

    float* __restrict__ outp = out + ((size_t)b * NK + (size_t)(dy * KS)) * HO * WO
                                   + (size_t)y * WO + lx;

    #pragma unroll
    for (int dx = 0; dx < KS; ++dx) {
        float4 v;
        v.x = (w[dx + 0] == c0) ? 1.0f : 0.0f;
        v.y = (w[dx + 1] == c1) ? 1.0f : 0.0f;
        v.z = (w[dx + 2] == c2) ? 1.0f : 0.0f;
        v.w = (w[dx + 3] == c3) ? 1.0f : 0.0f;
        *reinterpret_cast<float4*>(outp + (size_t)dx * HO * WO) = v;
    }
}

extern "C" void kernel_launch(void* const* d_in, const int* in_sizes, int n_in,
                              void* d_out, int out_size)
{
    const float* segments = (const float*)d_in[0];
    float* out = (float*)d_out;

    adj_equality_kernel<<<NBLK, 256, DYN_SMEM>>>(segments, out);
}

// round 6
// speedup vs baseline: 1.2144x; 1.0545x over previous
#include <cuda_runtime.h>
#include <cuda_bf16.h>
#include <cstddef>

#define RR   7
#define KS   15            // 2R+1
#define NK   (KS*KS)       // 225
#define BATCH 8
#define HI   512
#define WI   512
#define HO   256
#define WO   256
#define TY   4             // output rows per block
#define SW   (WO + 2*RR)   // 270 (x window with halo)
#define SWP  280           // padded smem row stride (multiple of 4 -> 16B rows)
#define NBLK (BATCH * (HO/TY) * KS)   // 8*64*15 = 7680
#define DYN_SMEM 46080     // caps occupancy at 4 CTAs/SM (4*46080=184KB <= 228KB)

__global__ __launch_bounds__(256)
void adj_equality_kernel(const float* __restrict__ in, float* __restrict__ out)
{
    extern __shared__ float nb[];   // uses nb[0 .. 4*SWP)

    // item decode: (b, ytile, dy) with dy fastest
    const int item = blockIdx.x;
    const int dy   = item % KS;
    const int sp   = item / KS;          // 0..511
    const int yt   = sp & 63;            // 0..63
    const int b    = sp >> 6;            // 0..7
    const int y0   = yt * TY;

    const int tid = threadIdx.x;
    const int tx  = tid & 63;            // 0..63
    const int ty  = tid >> 6;            // 0..3
    const int lx  = tx * 4;

    const float* __restrict__ inb = in + (size_t)b * HI * WI;

    // ---- Fill: row group r = ty fills smem row r, columns tx, tx+64, ... ----
    {
        const int ny = y0 + ty + dy - RR;
        const bool yok = (ny >= 0) && (ny < HO);
        const float* __restrict__ irow = inb + (size_t)(ny * 2) * WI;
        float* __restrict__ srow = nb + ty * SWP;
        #pragma unroll
        for (int k = 0; k < 5; ++k) {    // 5*64 = 320 >= 270
            const int c = tx + k * 64;
            if (c < SW) {
                const int gx = c - RR;
                float v = 0.0f;
                if (yok && gx >= 0 && gx < WO)
                    v = irow[(size_t)(gx * 2)];
                srow[c] = v;
            }
        }
    }

    // ---- Centers straight from global (L2-hot) ----
    const int y = y0 + ty;
    const float* __restrict__ crow = inb + (size_t)(y * 2) * WI;
    const float c0 = crow[(size_t)((lx + 0) * 2)];
    const float c1 = crow[(size_t)((lx + 1) * 2)];
    const float c2 = crow[(size_t)((lx + 2) * 2)];
    const float c3 = crow[(size_t)((lx + 3) * 2)];

    __syncthreads();

    // ---- Register window: 20 floats via 5x LDS.128 (16B-aligned, conflict-free) ----
    const float4* __restrict__ wrow =
        reinterpret_cast<const float4*>(nb + ty * SWP + lx);
    float w[20];
    #pragma unroll
    for (int q = 0; q < 5; ++q) {
        const float4 v = wrow[q];
        w[q * 4 + 0] = v.x;
        w[q * 4 + 1] = v.y;
        w[q * 4 + 2] = v.z;
        w[q * 4 + 3] = v.w;
    }

    float* __restrict__ outp = out + ((size_t)b * NK + (size_t)(dy * KS)) * HO * WO
                                   + (size_t)y * WO + lx;

    #pragma unroll
    for (int dx = 0; dx < KS; ++dx) {
        float4 v;
        v.x = (w[dx + 0] == c0) ? 1.0f : 0.0f;
        v.y = (w[dx + 1] == c1) ? 1.0f : 0.0f;
        v.z = (w[dx + 2] == c2) ? 1.0f : 0.0f;
        v.w = (w[dx + 3] == c3) ? 1.0f : 0.0f;
        // streaming store hint: evict-first dirty lines -> steadier L2->DRAM drain
        __stcs(reinterpret_cast<float4*>(outp + (size_t)dx * HO * WO), v);
    }
}

extern "C" void kernel_launch(void* const* d_in, const int* in_sizes, int n_in,
                              void* d_out, int out_size)
{
    const float* segments = (const float*)d_in[0];
    float* out = (float*)d_out;

    adj_equality_kernel<<<NBLK, 256, DYN_SMEM>>>(segments, out);
}